// round 5
// baseline (speedup 1.0000x reference)
#include <cuda_runtime.h>
#include <cuda_bf16.h>
#include <cstdint>

// Problem: InfoNCELoss, N=8192, D=256
static constexpr int N = 8192;
static constexpr int D = 256;
static constexpr float INV_T = 14.285714285714286f;   // 1/0.07
static constexpr float K1 = 20.609929156f;            // log2(e)/0.07
// exp((d-1)/T) = exp2(d*K1 - K1); valid since cos <= 1 (fixed-max trick)

static constexpr int BM = 256;
static constexpr int BN = 128;
static constexpr int NSPLIT = 4;
static constexpr int NTILES = (N / NSPLIT) / BN;      // 16
static constexpr int NHALVES = NTILES * 2;            // 32

// A: 256 rows x 256 bf16 (512B rows) resident = 128 KB
// B: two half-K buffers, each 128 rows x 128 bf16 (256B rows) = 32 KB
static constexpr int A_ROW_BYTES = 512;
static constexpr int B_ROW_BYTES = 256;
static constexpr int SMEM_A  = 0;
static constexpr int A_BYTES = BM * A_ROW_BYTES;          // 131072
static constexpr int B_BYTES = BN * B_ROW_BYTES;          // 32768
static constexpr int SMEM_B0 = A_BYTES;
static constexpr int SMEM_B1 = A_BYTES + B_BYTES;
static constexpr int SMEM_TOTAL = A_BYTES + 2 * B_BYTES;  // 196608

// Scratch (device globals: allocation-free rule)
__device__ __align__(128) __nv_bfloat16 g_un[N * D];
__device__ __align__(128) __nv_bfloat16 g_vn[N * D];
__device__ float g_diag[N];
__device__ float g_S[NSPLIT * N];

// ---------------------------------------------------------------------------
// helpers
// ---------------------------------------------------------------------------
__device__ __forceinline__ uint32_t smem_u32(const void* p) {
    uint32_t a;
    asm("{ .reg .u64 t; cvta.to.shared.u64 t, %1; cvt.u32.u64 %0, t; }"
        : "=r"(a) : "l"(p));
    return a;
}

// swizzled byte offsets; chunk c is a 16B unit within the row
__device__ __forceinline__ uint32_t swzA(uint32_t r, uint32_t c) {   // c in 0..31
    return r * A_ROW_BYTES + (((c & ~7u) | ((c ^ r) & 7u)) << 4);
}
__device__ __forceinline__ uint32_t swzB(uint32_t r, uint32_t c) {   // c in 0..15
    return r * B_ROW_BYTES + (((c & ~7u) | ((c ^ r) & 7u)) << 4);
}

__device__ __forceinline__ void ldsm_x4(uint32_t& r0, uint32_t& r1,
                                        uint32_t& r2, uint32_t& r3, uint32_t a) {
    asm volatile("ldmatrix.sync.aligned.m8n8.x4.shared.b16 {%0,%1,%2,%3}, [%4];"
                 : "=r"(r0), "=r"(r1), "=r"(r2), "=r"(r3) : "r"(a));
}

__device__ __forceinline__ void mma16816(float c[4], const uint32_t a[4],
                                         const uint32_t b[2]) {
    asm volatile(
        "mma.sync.aligned.m16n8k16.row.col.f32.bf16.bf16.f32 "
        "{%0,%1,%2,%3}, {%4,%5,%6,%7}, {%8,%9}, {%0,%1,%2,%3};\n"
        : "+f"(c[0]), "+f"(c[1]), "+f"(c[2]), "+f"(c[3])
        : "r"(a[0]), "r"(a[1]), "r"(a[2]), "r"(a[3]), "r"(b[0]), "r"(b[1]));
}

// Load resident A tile: 256 rows x 512B, 8192 chunks, 32 per thread
__device__ __forceinline__ void load_A(uint32_t smem_base,
                                       const __nv_bfloat16* gsrc, int t) {
    #pragma unroll
    for (int i = 0; i < 32; i++) {
        int idx = t + i * 256;
        uint32_t r = (uint32_t)idx >> 5;
        uint32_t c = (uint32_t)idx & 31;
        uint32_t dst = smem_base + swzA(r, c);
        const void* src = reinterpret_cast<const char*>(gsrc) + (size_t)idx * 16;
        asm volatile("cp.async.cg.shared.global [%0], [%1], 16;\n"
                     :: "r"(dst), "l"(src) : "memory");
    }
}

// Load one B half-tile: 128 rows x 256B (half of K), 2048 chunks, 8 per thread.
__device__ __forceinline__ void load_B_half(uint32_t smem_base,
                                            const __nv_bfloat16* gsrc,
                                            int h, int t) {
    #pragma unroll
    for (int i = 0; i < 8; i++) {
        int idx = t + i * 256;
        uint32_t r = (uint32_t)idx >> 4;   // row 0..127
        uint32_t c = (uint32_t)idx & 15;   // chunk in half-row
        uint32_t dst = smem_base + swzB(r, c);
        const void* src = reinterpret_cast<const char*>(gsrc)
                        + (size_t)r * A_ROW_BYTES + (size_t)h * 256 + (size_t)c * 16;
        asm volatile("cp.async.cg.shared.global [%0], [%1], 16;\n"
                     :: "r"(dst), "l"(src) : "memory");
    }
}

// ---------------------------------------------------------------------------
// Kernel 1: row-normalize, 2 rows per warp (MLP=8): bf16 outputs + fp32 diag
// ---------------------------------------------------------------------------
__device__ __forceinline__ uint32_t pack_bf2(float x, float y) {
    __nv_bfloat162 h = __float22bfloat162_rn(make_float2(x, y));
    return *reinterpret_cast<uint32_t*>(&h);
}

__global__ void normalize_kernel(const float* __restrict__ u,
                                 const float* __restrict__ v) {
    int t = threadIdx.x, w = t >> 5, lane = t & 31;
    int row = blockIdx.x * 16 + w * 2;           // this warp: rows row, row+1

    const float4* u0 = reinterpret_cast<const float4*>(u + (size_t)row * D);
    const float4* v0 = reinterpret_cast<const float4*>(v + (size_t)row * D);
    const float4* u1 = reinterpret_cast<const float4*>(u + (size_t)(row + 1) * D);
    const float4* v1 = reinterpret_cast<const float4*>(v + (size_t)(row + 1) * D);

    float4 a0 = u0[lane * 2], a1 = u0[lane * 2 + 1];
    float4 b0 = v0[lane * 2], b1 = v0[lane * 2 + 1];
    float4 c0 = u1[lane * 2], c1 = u1[lane * 2 + 1];
    float4 d0 = v1[lane * 2], d1 = v1[lane * 2 + 1];

    float su0 = a0.x*a0.x + a0.y*a0.y + a0.z*a0.z + a0.w*a0.w
              + a1.x*a1.x + a1.y*a1.y + a1.z*a1.z + a1.w*a1.w;
    float sv0 = b0.x*b0.x + b0.y*b0.y + b0.z*b0.z + b0.w*b0.w
              + b1.x*b1.x + b1.y*b1.y + b1.z*b1.z + b1.w*b1.w;
    float sd0 = a0.x*b0.x + a0.y*b0.y + a0.z*b0.z + a0.w*b0.w
              + a1.x*b1.x + a1.y*b1.y + a1.z*b1.z + a1.w*b1.w;
    float su1 = c0.x*c0.x + c0.y*c0.y + c0.z*c0.z + c0.w*c0.w
              + c1.x*c1.x + c1.y*c1.y + c1.z*c1.z + c1.w*c1.w;
    float sv1 = d0.x*d0.x + d0.y*d0.y + d0.z*d0.z + d0.w*d0.w
              + d1.x*d1.x + d1.y*d1.y + d1.z*d1.z + d1.w*d1.w;
    float sd1 = c0.x*d0.x + c0.y*d0.y + c0.z*d0.z + c0.w*d0.w
              + c1.x*d1.x + c1.y*d1.y + c1.z*d1.z + c1.w*d1.w;
    #pragma unroll
    for (int o = 16; o > 0; o >>= 1) {
        su0 += __shfl_xor_sync(0xffffffffu, su0, o);
        sv0 += __shfl_xor_sync(0xffffffffu, sv0, o);
        sd0 += __shfl_xor_sync(0xffffffffu, sd0, o);
        su1 += __shfl_xor_sync(0xffffffffu, su1, o);
        sv1 += __shfl_xor_sync(0xffffffffu, sv1, o);
        sd1 += __shfl_xor_sync(0xffffffffu, sd1, o);
    }
    float rnu0 = 1.0f / fmaxf(sqrtf(su0), 1e-8f);
    float rnv0 = 1.0f / fmaxf(sqrtf(sv0), 1e-8f);
    float rnu1 = 1.0f / fmaxf(sqrtf(su1), 1e-8f);
    float rnv1 = 1.0f / fmaxf(sqrtf(sv1), 1e-8f);

    uint4 p;
    p.x = pack_bf2(a0.x*rnu0, a0.y*rnu0); p.y = pack_bf2(a0.z*rnu0, a0.w*rnu0);
    p.z = pack_bf2(a1.x*rnu0, a1.y*rnu0); p.w = pack_bf2(a1.z*rnu0, a1.w*rnu0);
    *reinterpret_cast<uint4*>(&g_un[(size_t)row * D + lane * 8]) = p;
    p.x = pack_bf2(b0.x*rnv0, b0.y*rnv0); p.y = pack_bf2(b0.z*rnv0, b0.w*rnv0);
    p.z = pack_bf2(b1.x*rnv0, b1.y*rnv0); p.w = pack_bf2(b1.z*rnv0, b1.w*rnv0);
    *reinterpret_cast<uint4*>(&g_vn[(size_t)row * D + lane * 8]) = p;
    p.x = pack_bf2(c0.x*rnu1, c0.y*rnu1); p.y = pack_bf2(c0.z*rnu1, c0.w*rnu1);
    p.z = pack_bf2(c1.x*rnu1, c1.y*rnu1); p.w = pack_bf2(c1.z*rnu1, c1.w*rnu1);
    *reinterpret_cast<uint4*>(&g_un[(size_t)(row + 1) * D + lane * 8]) = p;
    p.x = pack_bf2(d0.x*rnv1, d0.y*rnv1); p.y = pack_bf2(d0.z*rnv1, d0.w*rnv1);
    p.z = pack_bf2(d1.x*rnv1, d1.y*rnv1); p.w = pack_bf2(d1.z*rnv1, d1.w*rnv1);
    *reinterpret_cast<uint4*>(&g_vn[(size_t)(row + 1) * D + lane * 8]) = p;
    if (lane == 0) {
        g_diag[row] = sd0 * rnu0 * rnv0;
        g_diag[row + 1] = sd1 * rnu1 * rnv1;
    }
}

// ---------------------------------------------------------------------------
// Kernel 2: fused GEMM + exp + row-sum, fragment-pipelined.
// grid (N/BM, NSPLIT) = (32, 4). 8 warps: wm=warp&3 (m), wn=warp>>2 (n).
// Warp tile 64x64; A resident in smem, B double-buffered per half-K;
// ldmatrix fragments double-buffered one k-step ahead.
// ---------------------------------------------------------------------------
__global__ __launch_bounds__(256, 1) void gemm_lse_kernel() {
    extern __shared__ char smem[];
    uint32_t sb = smem_u32(smem);

    const int t = threadIdx.x;
    const int lane = t & 31;
    const int warp = t >> 5;
    const int wm = warp & 3;
    const int wn = warp >> 2;
    const int gid = lane >> 2;
    const int tig = lane & 3;

    const int row0 = blockIdx.x * BM;
    const int col0 = blockIdx.y * (N / NSPLIT);

    // Prologue: A + tile0 halves
    load_A(sb + SMEM_A, &g_un[(size_t)row0 * D], t);
    asm volatile("cp.async.commit_group;" ::: "memory");
    load_B_half(sb + SMEM_B0, &g_vn[(size_t)col0 * D], 0, t);
    asm volatile("cp.async.commit_group;" ::: "memory");
    load_B_half(sb + SMEM_B1, &g_vn[(size_t)col0 * D], 1, t);
    asm volatile("cp.async.commit_group;" ::: "memory");

    // ldmatrix lane addressing
    const uint32_t a_rbase = (uint32_t)(wm * 64 + (lane & 15));
    const uint32_t a_d = (uint32_t)(lane >> 4);
    const uint32_t b_nbase = (uint32_t)(wn * 64 + ((lane & 16) >> 1) + (lane & 7));
    const uint32_t b_d = (uint32_t)((lane >> 3) & 1);

    float rsum[8];
    #pragma unroll
    for (int i = 0; i < 8; i++) rsum[i] = 0.f;

    #pragma unroll 1
    for (int j = 0; j < NTILES; j++) {
        float c[4][8][4];
        #pragma unroll
        for (int mi = 0; mi < 4; mi++)
            #pragma unroll
            for (int ni = 0; ni < 8; ni++)
                #pragma unroll
                for (int q = 0; q < 4; q++) c[mi][ni][q] = 0.f;

        #pragma unroll
        for (int h = 0; h < 2; h++) {
            asm volatile("cp.async.wait_group 1;" ::: "memory");
            __syncthreads();
            const uint32_t bsm = sb + (h ? SMEM_B1 : SMEM_B0);

            // double-buffered fragments, one k-step lookahead
            uint32_t fa[2][4][4], fb[2][8][2];

            // preload kk=0
            {
                const uint32_t chA = 2 * (h * 8) + a_d;
                const uint32_t chB = b_d;
                #pragma unroll
                for (int mi = 0; mi < 4; mi++)
                    ldsm_x4(fa[0][mi][0], fa[0][mi][1], fa[0][mi][2], fa[0][mi][3],
                            sb + SMEM_A + swzA(a_rbase + mi * 16, chA));
                #pragma unroll
                for (int q = 0; q < 4; q++) {
                    uint32_t r0, r1, r2, r3;
                    ldsm_x4(r0, r1, r2, r3, bsm + swzB(b_nbase + q * 16, chB));
                    fb[0][q * 2 + 0][0] = r0; fb[0][q * 2 + 0][1] = r1;
                    fb[0][q * 2 + 1][0] = r2; fb[0][q * 2 + 1][1] = r3;
                }
            }

            #pragma unroll
            for (int kk = 0; kk < 8; kk++) {
                const int cur = kk & 1, nxt = cur ^ 1;
                if (kk < 7) {
                    const uint32_t chA = 2 * (h * 8 + kk + 1) + a_d;
                    const uint32_t chB = 2 * (kk + 1) + b_d;
                    #pragma unroll
                    for (int mi = 0; mi < 4; mi++)
                        ldsm_x4(fa[nxt][mi][0], fa[nxt][mi][1],
                                fa[nxt][mi][2], fa[nxt][mi][3],
                                sb + SMEM_A + swzA(a_rbase + mi * 16, chA));
                    #pragma unroll
                    for (int q = 0; q < 4; q++) {
                        uint32_t r0, r1, r2, r3;
                        ldsm_x4(r0, r1, r2, r3, bsm + swzB(b_nbase + q * 16, chB));
                        fb[nxt][q * 2 + 0][0] = r0; fb[nxt][q * 2 + 0][1] = r1;
                        fb[nxt][q * 2 + 1][0] = r2; fb[nxt][q * 2 + 1][1] = r3;
                    }
                }
                #pragma unroll
                for (int mi = 0; mi < 4; mi++)
                    #pragma unroll
                    for (int ni = 0; ni < 8; ni++)
                        mma16816(c[mi][ni], fa[cur][mi], fb[cur][ni]);
            }

            __syncthreads();   // done reading buffer h

            // prefetch next half (global half index 2j + h + 2) into buffer h
            const int nh = 2 * j + h + 2;
            if (nh < NHALVES)
                load_B_half(sb + (h ? SMEM_B1 : SMEM_B0),
                            &g_vn[(size_t)(col0 + (nh >> 1) * BN) * D],
                            nh & 1, t);
            asm volatile("cp.async.commit_group;" ::: "memory");
        }

        // epilogue: exp2(d*K1 - K1), accumulate row sums (overlaps prefetch)
        #pragma unroll
        for (int mi = 0; mi < 4; mi++) {
            #pragma unroll
            for (int ni = 0; ni < 8; ni++) {
                rsum[mi * 2 + 0] += exp2f(fmaf(c[mi][ni][0], K1, -K1))
                                  + exp2f(fmaf(c[mi][ni][1], K1, -K1));
                rsum[mi * 2 + 1] += exp2f(fmaf(c[mi][ni][2], K1, -K1))
                                  + exp2f(fmaf(c[mi][ni][3], K1, -K1));
            }
        }
    }

    // Reduce across the 4 lanes (tig) sharing each row
    #pragma unroll
    for (int x = 0; x < 8; x++) {
        rsum[x] += __shfl_xor_sync(0xffffffffu, rsum[x], 1);
        rsum[x] += __shfl_xor_sync(0xffffffffu, rsum[x], 2);
    }

    __syncthreads();   // done with smem tiles; reuse A region
    float* Ssum = reinterpret_cast<float*>(smem);   // [2][BM]
    if (tig == 0) {
        #pragma unroll
        for (int mi = 0; mi < 4; mi++)
            #pragma unroll
            for (int hh = 0; hh < 2; hh++) {
                int r = wm * 64 + mi * 16 + hh * 8 + gid;
                Ssum[wn * BM + r] = rsum[mi * 2 + hh];
            }
    }
    __syncthreads();
    g_S[blockIdx.y * N + row0 + t] = Ssum[t] + Ssum[BM + t];
}

// ---------------------------------------------------------------------------
// Kernel 3: loss = mean(log(sum_s S[s]) + (1 - diag)/T)
// ---------------------------------------------------------------------------
__global__ void finalize_kernel(float* __restrict__ out) {
    int t = threadIdx.x;
    float acc = 0.0f;
    for (int i = t; i < N; i += 1024) {
        float S = g_S[i] + g_S[N + i] + g_S[2 * N + i] + g_S[3 * N + i];
        acc += logf(S) + (1.0f - g_diag[i]) * INV_T;
    }
    #pragma unroll
    for (int o = 16; o > 0; o >>= 1) acc += __shfl_xor_sync(0xffffffffu, acc, o);
    __shared__ float sh[32];
    int lane = t & 31, w = t >> 5;
    if (lane == 0) sh[w] = acc;
    __syncthreads();
    if (t == 0) {
        float total = 0.0f;
        #pragma unroll
        for (int i = 0; i < 32; i++) total += sh[i];
        out[0] = total / (float)N;
    }
}

// ---------------------------------------------------------------------------
extern "C" void kernel_launch(void* const* d_in, const int* in_sizes, int n_in,
                              void* d_out, int out_size) {
    const float* u = (const float*)d_in[0];
    const float* v = (const float*)d_in[1];
    float* out = (float*)d_out;

    cudaFuncSetAttribute(gemm_lse_kernel,
                         cudaFuncAttributeMaxDynamicSharedMemorySize, SMEM_TOTAL);

    normalize_kernel<<<N / 16, 256>>>(u, v);
    dim3 grid(N / BM, NSPLIT);
    gemm_lse_kernel<<<grid, 256, SMEM_TOTAL>>>();
    finalize_kernel<<<1, 1024>>>(out);
}